// round 2
// baseline (speedup 1.0000x reference)
#include <cuda_runtime.h>
#include <math.h>

// ---------------- problem constants ----------------
#define G_NUM 50
#define NPER  1000
#define HDIM  128
#define K1    600
#define K2    360
#define K3    216
#define N1    (G_NUM*NPER)   // 50000
#define N2    (G_NUM*K1)     // 30000
#define N3    (G_NUM*K2)     // 18000
#define N4    (G_NUM*K3)     // 10800
#define EMAX  800000
#define CAP   96             // max in-degree bucket (Poisson(16); P(>=96) ~ 1e-44)
#define FINF  3.402823466e38f

// ---------------- scratch (device globals; no allocation allowed) ----------------
__device__ float g_hl[(size_t)N1*HDIM];   // linear features  h = x @ W^T
__device__ float g_h [(size_t)N1*HDIM];   // GAT output (post relu)
__device__ float g_hp[(size_t)N2*HDIM];   // pooled features
__device__ float g_as[N1];
__device__ float g_ad[N1];
__device__ float g_sc[N1];
__device__ int   g_deg[N1];
__device__ int   g_adj[(size_t)N1*CAP];
__device__ int   g_perm[N2];
__device__ int   g_map[N1];
__device__ int   g_srcA[EMAX], g_dstA[EMAX];
__device__ int   g_srcB[EMAX], g_dstB[EMAX];
__device__ unsigned char g_valA[EMAX], g_valB[EMAX];
__device__ float g_z[G_NUM*256];
__device__ float g_norms[2];

// ---------------- small utility kernels ----------------
__global__ void zeroI_k(int* p, int n) {
    int i = blockIdx.x*blockDim.x + threadIdx.x;
    if (i < n) p[i] = 0;
}
__global__ void zeroF_k(float* p, int n) {
    int i = blockIdx.x*blockDim.x + threadIdx.x;
    if (i < n) p[i] = 0.f;
}
// reciprocal norms of p1, p2
__global__ void norms_k(const float* __restrict__ p1, const float* __restrict__ p2,
                        float* __restrict__ out) {
    __shared__ float s1[128], s2[128];
    int t = threadIdx.x;
    s1[t] = p1[t]*p1[t];
    s2[t] = p2[t]*p2[t];
    __syncthreads();
    for (int o = 64; o > 0; o >>= 1) {
        if (t < o) { s1[t] += s1[t+o]; s2[t] += s2[t+o]; }
        __syncthreads();
    }
    if (t == 0) { out[0] = rsqrtf(s1[0]); out[1] = rsqrtf(s2[0]); }
}

// ---------------- GEMM: Y[M,128] = X[M,128] @ W[128,128]^T ----------------
#define LDS_X 132
#define LDS_W 132
#define GEMM_SMEM ((128*LDS_X + 128*LDS_W)*4)

__global__ void gemm128_k(const float* __restrict__ X, const float* __restrict__ W,
                          float* __restrict__ Y, int M)
{
    extern __shared__ float sm[];
    float* Xs = sm;                 // [row][k]  row-major, padded
    float* Ws = sm + 128*LDS_X;     // [k][c]    transposed W
    int tid = threadIdx.x;
    int rowBase = blockIdx.x * 128;

    // load X tile (128 rows x 128 k = 4096 float4 slots), rows clamped for tail
    #pragma unroll
    for (int i = 0; i < 16; i++) {
        int v  = tid + i*256;      // 0..4095 float4 slots
        int r  = v >> 5;
        int k4 = v & 31;
        int gr = rowBase + r; if (gr >= M) gr = M - 1;
        float4 x4 = *reinterpret_cast<const float4*>(X + (size_t)gr*128 + k4*4);
        float* d = Xs + r*LDS_X + k4*4;
        d[0] = x4.x; d[1] = x4.y; d[2] = x4.z; d[3] = x4.w;
    }
    // load W transposed: Ws[k][c] = W[c][k]   (4096 float4 slots)
    #pragma unroll
    for (int i = 0; i < 16; i++) {
        int v  = tid + i*256;
        int c  = v >> 5;
        int k4 = v & 31;
        float4 w4 = *reinterpret_cast<const float4*>(W + (size_t)c*128 + k4*4);
        Ws[(k4*4+0)*LDS_W + c] = w4.x;
        Ws[(k4*4+1)*LDS_W + c] = w4.y;
        Ws[(k4*4+2)*LDS_W + c] = w4.z;
        Ws[(k4*4+3)*LDS_W + c] = w4.w;
    }
    __syncthreads();

    int tx = tid & 15, ty = tid >> 4;   // 16x16 threads, 8 rows x 8 cols each
    float acc[8][8];
    #pragma unroll
    for (int i = 0; i < 8; i++)
        #pragma unroll
        for (int j = 0; j < 8; j++) acc[i][j] = 0.f;

    #pragma unroll 4
    for (int k = 0; k < 128; k++) {
        float a[8];
        #pragma unroll
        for (int i = 0; i < 8; i++) a[i] = Xs[(ty*8 + i)*LDS_X + k];
        float4 b0 = *reinterpret_cast<const float4*>(Ws + k*LDS_W + tx*4);
        float4 b1 = *reinterpret_cast<const float4*>(Ws + k*LDS_W + 64 + tx*4);
        #pragma unroll
        for (int i = 0; i < 8; i++) {
            acc[i][0] += a[i]*b0.x; acc[i][1] += a[i]*b0.y;
            acc[i][2] += a[i]*b0.z; acc[i][3] += a[i]*b0.w;
            acc[i][4] += a[i]*b1.x; acc[i][5] += a[i]*b1.y;
            acc[i][6] += a[i]*b1.z; acc[i][7] += a[i]*b1.w;
        }
    }
    #pragma unroll
    for (int i = 0; i < 8; i++) {
        int r = rowBase + ty*8 + i;
        if (r < M) {
            *reinterpret_cast<float4*>(Y + (size_t)r*128 + tx*4) =
                make_float4(acc[i][0], acc[i][1], acc[i][2], acc[i][3]);
            *reinterpret_cast<float4*>(Y + (size_t)r*128 + 64 + tx*4) =
                make_float4(acc[i][4], acc[i][5], acc[i][6], acc[i][7]);
        }
    }
}

// ---------------- per-node attention dots: as[i]=h_i.aS, ad[i]=h_i.aD ----------------
__global__ void dots_k(const float* __restrict__ h, const float* __restrict__ aS,
                       const float* __restrict__ aD, float* __restrict__ asv,
                       float* __restrict__ adv, int N)
{
    int w = (blockIdx.x*blockDim.x + threadIdx.x) >> 5;
    int lane = threadIdx.x & 31;
    if (w >= N) return;
    float4 hv = *reinterpret_cast<const float4*>(h + (size_t)w*128 + lane*4);
    float4 a4 = *reinterpret_cast<const float4*>(aS + lane*4);
    float4 d4 = *reinterpret_cast<const float4*>(aD + lane*4);
    float sa = hv.x*a4.x + hv.y*a4.y + hv.z*a4.z + hv.w*a4.w;
    float sd = hv.x*d4.x + hv.y*d4.y + hv.z*d4.z + hv.w*d4.w;
    #pragma unroll
    for (int o = 16; o > 0; o >>= 1) {
        sa += __shfl_xor_sync(0xffffffffu, sa, o);
        sd += __shfl_xor_sync(0xffffffffu, sd, o);
    }
    if (lane == 0) { asv[w] = sa; adv[w] = sd; }
}

// ---------------- build adjacency (and optionally remap edges through pooling map) ----
__global__ void build_remap_k(const int* __restrict__ src, const int* __restrict__ dst,
                              const unsigned char* __restrict__ validIn, int E,
                              const int* __restrict__ map,
                              int* __restrict__ srcOut, int* __restrict__ dstOut,
                              unsigned char* __restrict__ valOut,
                              int* __restrict__ deg, int* __restrict__ adj)
{
    int e = blockIdx.x*blockDim.x + threadIdx.x;
    if (e >= E) return;
    unsigned char v = validIn ? validIn[e] : (unsigned char)1;
    int ns = 0, nd = 0;
    unsigned char ok = 0;
    if (v) {
        int s = src[e], d = dst[e];
        if (map) {
            ns = map[s]; nd = map[d];
            ok = (ns >= 0 && nd >= 0) ? 1 : 0;
        } else {
            ns = s; nd = d; ok = 1;
        }
    }
    if (srcOut) {
        srcOut[e] = ok ? ns : 0;
        dstOut[e] = ok ? nd : 0;
        valOut[e] = ok;
    }
    if (ok) {
        int pos = atomicAdd(&deg[nd], 1);
        if (pos < CAP) adj[(size_t)nd*CAP + pos] = ns;
    }
}

// ---------------- GAT aggregation (softmax over incoming edges + self-loop) ----------
__global__ void gat_agg_k(const float* __restrict__ hl, const float* __restrict__ asv,
                          const float* __restrict__ adv, const int* __restrict__ adj,
                          const int* __restrict__ deg, const float* __restrict__ b,
                          float* __restrict__ out, int N)
{
    int d = (blockIdx.x*blockDim.x + threadIdx.x) >> 5;
    int lane = threadIdx.x & 31;
    if (d >= N) return;
    float add = adv[d];
    // self loop
    float l = asv[d] + add; l = (l > 0.f) ? l : 0.2f*l;
    float w = __expf(l);
    float den = w;
    float4 hv = *reinterpret_cast<const float4*>(hl + (size_t)d*128 + lane*4);
    float4 acc = make_float4(w*hv.x, w*hv.y, w*hv.z, w*hv.w);
    int dg = deg[d]; if (dg > CAP) dg = CAP;
    const int* row = adj + (size_t)d*CAP;
    for (int j = 0; j < dg; j++) {
        int s = row[j];
        float l2 = asv[s] + add; l2 = (l2 > 0.f) ? l2 : 0.2f*l2;
        float w2 = __expf(l2);
        den += w2;
        float4 g = *reinterpret_cast<const float4*>(hl + (size_t)s*128 + lane*4);
        acc.x += w2*g.x; acc.y += w2*g.y; acc.z += w2*g.z; acc.w += w2*g.w;
    }
    float inv = 1.f/den;
    float4 bb = *reinterpret_cast<const float4*>(b + lane*4);
    float4 o;
    o.x = fmaxf(acc.x*inv + bb.x, 0.f);
    o.y = fmaxf(acc.y*inv + bb.y, 0.f);
    o.z = fmaxf(acc.z*inv + bb.z, 0.f);
    o.w = fmaxf(acc.w*inv + bb.w, 0.f);
    *reinterpret_cast<float4*>(out + (size_t)d*128 + lane*4) = o;
}

// ---------------- pooling score: sc[i] = (h_i . p) / ||p|| ----------------
__global__ void score_k(const float* __restrict__ h, const float* __restrict__ p,
                        const float* __restrict__ nrm, int idx,
                        float* __restrict__ sc, int N)
{
    int w = (blockIdx.x*blockDim.x + threadIdx.x) >> 5;
    int lane = threadIdx.x & 31;
    if (w >= N) return;
    float4 hv = *reinterpret_cast<const float4*>(h + (size_t)w*128 + lane*4);
    float4 p4 = *reinterpret_cast<const float4*>(p + lane*4);
    float s = hv.x*p4.x + hv.y*p4.y + hv.z*p4.z + hv.w*p4.w;
    #pragma unroll
    for (int o = 16; o > 0; o >>= 1) s += __shfl_xor_sync(0xffffffffu, s, o);
    if (lane == 0) sc[w] = s * nrm[idx];
}

// ---------------- per-graph top-k (bitonic sort; npad = blockDim.x pow2) -------------
__global__ void topk_k(const float* __restrict__ sc, int n, int k,
                       int* __restrict__ perm, int* __restrict__ map)
{
    __shared__ float sval[1024];
    __shared__ int   sidx[1024];
    int g = blockIdx.x, t = threadIdx.x, npad = blockDim.x;
    sval[t] = (t < n) ? sc[g*n + t] : -FINF;
    sidx[t] = t;
    if (t < n) map[g*n + t] = -1;
    __syncthreads();
    for (int kk = 2; kk <= npad; kk <<= 1) {
        for (int j = kk >> 1; j > 0; j >>= 1) {
            int ixj = t ^ j;
            if (ixj > t) {
                bool desc = ((t & kk) == 0);
                float v1 = sval[t], v2 = sval[ixj];
                bool sw = desc ? (v1 < v2) : (v1 > v2);
                if (sw) {
                    sval[t] = v2; sval[ixj] = v1;
                    int tmp = sidx[t]; sidx[t] = sidx[ixj]; sidx[ixj] = tmp;
                }
            }
            __syncthreads();
        }
    }
    if (t < k) {
        int old = g*n + sidx[t];
        perm[g*k + t] = old;
        map[old] = g*k + t;
    }
}

// ---------------- gather pooled features: hp[new] = h[old]*tanh(sc[old]) -------------
__global__ void gather_k(const float* __restrict__ h, const float* __restrict__ sc,
                         const int* __restrict__ perm, float* __restrict__ hp, int Nnew)
{
    int w = (blockIdx.x*blockDim.x + threadIdx.x) >> 5;
    int lane = threadIdx.x & 31;
    if (w >= Nnew) return;
    int old = perm[w];
    float gsc = tanhf(sc[old]);
    float4 v = *reinterpret_cast<const float4*>(h + (size_t)old*128 + lane*4);
    v.x *= gsc; v.y *= gsc; v.z *= gsc; v.w *= gsc;
    *reinterpret_cast<float4*>(hp + (size_t)w*128 + lane*4) = v;
}

// ---------------- readout: z[g] += [max | mean] over k rows ----------------
__global__ void readout_k(const float* __restrict__ hp, float* __restrict__ z, int k)
{
    int g = blockIdx.x, t = threadIdx.x;   // 128 threads
    const float* base = hp + (size_t)g*k*128 + t;
    float m = -FINF, s = 0.f;
    for (int r = 0; r < k; r++) {
        float v = base[(size_t)r*128];
        m = fmaxf(m, v);
        s += v;
    }
    z[g*256 + t]       += m;
    z[g*256 + 128 + t] += s / (float)k;
}

// ---------------- final MLP + log_softmax ----------------
__global__ void mlp_k(const float* __restrict__ z,
                      const float* __restrict__ lw1, const float* __restrict__ lb1,
                      const float* __restrict__ lw2, const float* __restrict__ lb2,
                      const float* __restrict__ lw3, const float* __restrict__ lb3,
                      float* __restrict__ out)
{
    __shared__ float zr[256], t1[128], t2[64], o[10], red[2];
    int g = blockIdx.x, t = threadIdx.x;   // 256 threads
    zr[t] = z[g*256 + t];
    __syncthreads();
    if (t < 128) {
        float a = lb1[t];
        const float* w = lw1 + t*256;
        for (int j = 0; j < 256; j++) a += zr[j]*w[j];
        t1[t] = fmaxf(a, 0.f);
    }
    __syncthreads();
    if (t < 64) {
        float a = lb2[t];
        const float* w = lw2 + t*128;
        for (int j = 0; j < 128; j++) a += t1[j]*w[j];
        t2[t] = fmaxf(a, 0.f);
    }
    __syncthreads();
    if (t < 10) {
        float a = lb3[t];
        const float* w = lw3 + t*64;
        for (int j = 0; j < 64; j++) a += t2[j]*w[j];
        o[t] = a;
    }
    __syncthreads();
    if (t == 0) {
        float m = -FINF;
        for (int i = 0; i < 10; i++) m = fmaxf(m, o[i]);
        float s = 0.f;
        for (int i = 0; i < 10; i++) s += expf(o[i] - m);
        red[0] = m; red[1] = logf(s);
    }
    __syncthreads();
    if (t < 10) out[g*10 + t] = o[t] - red[0] - red[1];
}

// ---------------- host driver ----------------
static inline int cdiv(int a, int b) { return (a + b - 1) / b; }

extern "C" void kernel_launch(void* const* d_in, const int* in_sizes, int n_in,
                              void* d_out, int out_size)
{
    const float* x   = (const float*)d_in[0];
    const int*   ei  = (const int*)  d_in[1];
    const float* W1  = (const float*)d_in[2];
    const float* aS1 = (const float*)d_in[3];
    const float* aD1 = (const float*)d_in[4];
    const float* b1  = (const float*)d_in[5];
    const float* W2  = (const float*)d_in[6];
    const float* aS2 = (const float*)d_in[7];
    const float* aD2 = (const float*)d_in[8];
    const float* b2  = (const float*)d_in[9];
    const float* W3  = (const float*)d_in[10];
    const float* aS3 = (const float*)d_in[11];
    const float* aD3 = (const float*)d_in[12];
    const float* b3  = (const float*)d_in[13];
    const float* p1  = (const float*)d_in[14];
    const float* p2  = (const float*)d_in[15];
    const float* lw1 = (const float*)d_in[16];
    const float* lb1 = (const float*)d_in[17];
    const float* lw2 = (const float*)d_in[18];
    const float* lb2 = (const float*)d_in[19];
    const float* lw3 = (const float*)d_in[20];
    const float* lb3 = (const float*)d_in[21];
    float* out = (float*)d_out;

    const int E = in_sizes[1] / 2;

    void *p_hl, *p_h, *p_hp, *p_as, *p_ad, *p_sc, *p_deg, *p_adj, *p_perm, *p_map;
    void *p_srcA, *p_dstA, *p_valA, *p_srcB, *p_dstB, *p_valB, *p_z, *p_nrm;
    cudaGetSymbolAddress(&p_hl, g_hl);   cudaGetSymbolAddress(&p_h, g_h);
    cudaGetSymbolAddress(&p_hp, g_hp);   cudaGetSymbolAddress(&p_as, g_as);
    cudaGetSymbolAddress(&p_ad, g_ad);   cudaGetSymbolAddress(&p_sc, g_sc);
    cudaGetSymbolAddress(&p_deg, g_deg); cudaGetSymbolAddress(&p_adj, g_adj);
    cudaGetSymbolAddress(&p_perm, g_perm); cudaGetSymbolAddress(&p_map, g_map);
    cudaGetSymbolAddress(&p_srcA, g_srcA); cudaGetSymbolAddress(&p_dstA, g_dstA);
    cudaGetSymbolAddress(&p_valA, g_valA); cudaGetSymbolAddress(&p_srcB, g_srcB);
    cudaGetSymbolAddress(&p_dstB, g_dstB); cudaGetSymbolAddress(&p_valB, g_valB);
    cudaGetSymbolAddress(&p_z, g_z);       cudaGetSymbolAddress(&p_nrm, g_norms);

    float* hl  = (float*)p_hl;  float* h   = (float*)p_h;   float* hp = (float*)p_hp;
    float* asv = (float*)p_as;  float* adv = (float*)p_ad;  float* sc = (float*)p_sc;
    int* deg = (int*)p_deg;     int* adj = (int*)p_adj;
    int* perm = (int*)p_perm;   int* mp = (int*)p_map;
    int* srcA = (int*)p_srcA;   int* dstA = (int*)p_dstA;
    unsigned char* valA = (unsigned char*)p_valA;
    int* srcB = (int*)p_srcB;   int* dstB = (int*)p_dstB;
    unsigned char* valB = (unsigned char*)p_valB;
    float* z = (float*)p_z;     float* nrm = (float*)p_nrm;

    cudaFuncSetAttribute(gemm128_k, cudaFuncAttributeMaxDynamicSharedMemorySize, GEMM_SMEM);

    norms_k<<<1, 128>>>(p1, p2, nrm);
    zeroF_k<<<cdiv(G_NUM*256, 256), 256>>>(z, G_NUM*256);

    // ---------- stage 1 ----------
    gemm128_k<<<cdiv(N1, 128), 256, GEMM_SMEM>>>(x, W1, hl, N1);
    dots_k<<<cdiv(N1, 8), 256>>>(hl, aS1, aD1, asv, adv, N1);
    zeroI_k<<<cdiv(N1, 256), 256>>>(deg, N1);
    build_remap_k<<<cdiv(E, 256), 256>>>(ei, ei + E, nullptr, E, nullptr,
                                         nullptr, nullptr, nullptr, deg, adj);
    gat_agg_k<<<cdiv(N1, 8), 256>>>(hl, asv, adv, adj, deg, b1, h, N1);
    score_k<<<cdiv(N1, 8), 256>>>(h, p1, nrm, 0, sc, N1);
    topk_k<<<G_NUM, 1024>>>(sc, NPER, K1, perm, mp);
    gather_k<<<cdiv(N2, 8), 256>>>(h, sc, perm, hp, N2);
    readout_k<<<G_NUM, 128>>>(hp, z, K1);
    zeroI_k<<<cdiv(N2, 256), 256>>>(deg, N2);
    build_remap_k<<<cdiv(E, 256), 256>>>(ei, ei + E, nullptr, E, mp,
                                         srcA, dstA, valA, deg, adj);

    // ---------- stage 2 ----------
    gemm128_k<<<cdiv(N2, 128), 256, GEMM_SMEM>>>(hp, W2, hl, N2);
    dots_k<<<cdiv(N2, 8), 256>>>(hl, aS2, aD2, asv, adv, N2);
    gat_agg_k<<<cdiv(N2, 8), 256>>>(hl, asv, adv, adj, deg, b2, h, N2);
    score_k<<<cdiv(N2, 8), 256>>>(h, p2, nrm, 1, sc, N2);
    topk_k<<<G_NUM, 1024>>>(sc, K1, K2, perm, mp);
    gather_k<<<cdiv(N3, 8), 256>>>(h, sc, perm, hp, N3);
    readout_k<<<G_NUM, 128>>>(hp, z, K2);
    zeroI_k<<<cdiv(N3, 256), 256>>>(deg, N3);
    build_remap_k<<<cdiv(E, 256), 256>>>(srcA, dstA, valA, E, mp,
                                         srcB, dstB, valB, deg, adj);

    // ---------- stage 3 ----------
    gemm128_k<<<cdiv(N3, 128), 256, GEMM_SMEM>>>(hp, W3, hl, N3);
    dots_k<<<cdiv(N3, 8), 256>>>(hl, aS3, aD3, asv, adv, N3);
    gat_agg_k<<<cdiv(N3, 8), 256>>>(hl, asv, adv, adj, deg, b3, h, N3);
    score_k<<<cdiv(N3, 8), 256>>>(h, p2, nrm, 1, sc, N3);
    topk_k<<<G_NUM, 512>>>(sc, K2, K3, perm, mp);
    gather_k<<<cdiv(N4, 8), 256>>>(h, sc, perm, hp, N4);
    readout_k<<<G_NUM, 128>>>(hp, z, K3);

    // ---------- head ----------
    mlp_k<<<G_NUM, 256>>>(z, lw1, lb1, lw2, lb2, lw3, lb3, out);
}

// round 3
// speedup vs baseline: 1.0661x; 1.0661x over previous
#include <cuda_runtime.h>
#include <math.h>

// ---------------- problem constants ----------------
#define G_NUM 50
#define NPER  1000
#define HDIM  128
#define K1    600
#define K2    360
#define K3    216
#define N1    (G_NUM*NPER)   // 50000
#define N2    (G_NUM*K1)     // 30000
#define N3    (G_NUM*K2)     // 18000
#define N4    (G_NUM*K3)     // 10800
#define EMAX  800000
#define CAP   96             // max in-degree bucket (Poisson(16); P(>=96) ~ 1e-44)
#define FINF  3.402823466e38f

// ---------------- scratch (device globals; no allocation allowed) ----------------
__device__ float g_hl[(size_t)N1*HDIM];   // linear features  h = x @ W^T
__device__ float g_h [(size_t)N1*HDIM];   // GAT output (post relu)
__device__ float g_hp[(size_t)N2*HDIM];   // pooled features
__device__ float g_as[N1];
__device__ float g_ad[N1];
__device__ float g_sc[N1];
__device__ int   g_deg[N1];
__device__ int   g_adj[(size_t)N1*CAP];
__device__ int   g_perm[N2];
__device__ int   g_gmap[N1];              // orig-id -> current-id (composed)
__device__ int   g_map2[N2];              // per-stage local map
__device__ float g_z[G_NUM*256];
__device__ float g_norms[2];

// ---------------- small utility kernels ----------------
__global__ void zeroI_k(int* p, int n) {
    int i = blockIdx.x*blockDim.x + threadIdx.x;
    if (i < n) p[i] = 0;
}
// reciprocal norms of p1, p2
__global__ void norms_k(const float* __restrict__ p1, const float* __restrict__ p2,
                        float* __restrict__ out) {
    __shared__ float s1[128], s2[128];
    int t = threadIdx.x;
    s1[t] = p1[t]*p1[t];
    s2[t] = p2[t]*p2[t];
    __syncthreads();
    for (int o = 64; o > 0; o >>= 1) {
        if (t < o) { s1[t] += s1[t+o]; s2[t] += s2[t+o]; }
        __syncthreads();
    }
    if (t == 0) { out[0] = rsqrtf(s1[0]); out[1] = rsqrtf(s2[0]); }
}

// ---------------- GEMM: Y[M,128] = X[M,128] @ W[128,128]^T, fused attention dots ----
#define LDS_X 132
#define LDS_W 132
#define GEMM_SMEM ((128*LDS_X + 128*LDS_W)*4)

__global__ void __launch_bounds__(256, 1)
gemm128_k(const float* __restrict__ X, const float* __restrict__ W,
          float* __restrict__ Y, int M,
          const float* __restrict__ aS, const float* __restrict__ aD,
          float* __restrict__ asv, float* __restrict__ adv)
{
    extern __shared__ float sm[];
    float* Xs = sm;                 // [row][k]  row-major, padded
    float* Ws = sm + 128*LDS_X;     // [k][c]    transposed W
    int tid = threadIdx.x;
    int rowBase = blockIdx.x * 128;

    // load X tile (128 rows x 128 k = 4096 float4 slots), rows clamped for tail
    #pragma unroll
    for (int i = 0; i < 16; i++) {
        int v  = tid + i*256;      // 0..4095 float4 slots
        int r  = v >> 5;
        int k4 = v & 31;
        int gr = rowBase + r; if (gr >= M) gr = M - 1;
        float4 x4 = *reinterpret_cast<const float4*>(X + (size_t)gr*128 + k4*4);
        float* d = Xs + r*LDS_X + k4*4;
        d[0] = x4.x; d[1] = x4.y; d[2] = x4.z; d[3] = x4.w;
    }
    // load W transposed: Ws[k][c] = W[c][k]   (4096 float4 slots)
    #pragma unroll
    for (int i = 0; i < 16; i++) {
        int v  = tid + i*256;
        int c  = v >> 5;
        int k4 = v & 31;
        float4 w4 = *reinterpret_cast<const float4*>(W + (size_t)c*128 + k4*4);
        Ws[(k4*4+0)*LDS_W + c] = w4.x;
        Ws[(k4*4+1)*LDS_W + c] = w4.y;
        Ws[(k4*4+2)*LDS_W + c] = w4.z;
        Ws[(k4*4+3)*LDS_W + c] = w4.w;
    }
    __syncthreads();

    int tx = tid & 15, ty = tid >> 4;   // 16x16 threads, 8 rows x 8 cols each
    float acc[8][8];
    #pragma unroll
    for (int i = 0; i < 8; i++)
        #pragma unroll
        for (int j = 0; j < 8; j++) acc[i][j] = 0.f;

    #pragma unroll 2
    for (int kk = 0; kk < 128; kk += 4) {
        float4 a4[8];
        #pragma unroll
        for (int i = 0; i < 8; i++)
            a4[i] = *reinterpret_cast<const float4*>(Xs + (ty*8 + i)*LDS_X + kk);
        #pragma unroll
        for (int q = 0; q < 4; q++) {
            float4 b0 = *reinterpret_cast<const float4*>(Ws + (kk+q)*LDS_W + tx*4);
            float4 b1 = *reinterpret_cast<const float4*>(Ws + (kk+q)*LDS_W + 64 + tx*4);
            #pragma unroll
            for (int i = 0; i < 8; i++) {
                float av = (q == 0) ? a4[i].x : (q == 1) ? a4[i].y : (q == 2) ? a4[i].z : a4[i].w;
                acc[i][0] += av*b0.x; acc[i][1] += av*b0.y;
                acc[i][2] += av*b0.z; acc[i][3] += av*b0.w;
                acc[i][4] += av*b1.x; acc[i][5] += av*b1.y;
                acc[i][6] += av*b1.z; acc[i][7] += av*b1.w;
            }
        }
    }

    // epilogue: store Y + fused per-row dots with aS/aD
    float aSv[8], aDv[8];
    #pragma unroll
    for (int j = 0; j < 4; j++) {
        aSv[j]   = aS[tx*4 + j];      aSv[4+j] = aS[64 + tx*4 + j];
        aDv[j]   = aD[tx*4 + j];      aDv[4+j] = aD[64 + tx*4 + j];
    }
    int lane = tid & 31;
    #pragma unroll
    for (int i = 0; i < 8; i++) {
        int r = rowBase + ty*8 + i;
        bool ok = (r < M);
        if (ok) {
            *reinterpret_cast<float4*>(Y + (size_t)r*128 + tx*4) =
                make_float4(acc[i][0], acc[i][1], acc[i][2], acc[i][3]);
            *reinterpret_cast<float4*>(Y + (size_t)r*128 + 64 + tx*4) =
                make_float4(acc[i][4], acc[i][5], acc[i][6], acc[i][7]);
        }
        float pa = 0.f, pd = 0.f;
        #pragma unroll
        for (int j = 0; j < 8; j++) { pa += acc[i][j]*aSv[j]; pd += acc[i][j]*aDv[j]; }
        #pragma unroll
        for (int o = 8; o > 0; o >>= 1) {
            pa += __shfl_xor_sync(0xffffffffu, pa, o);
            pd += __shfl_xor_sync(0xffffffffu, pd, o);
        }
        if (ok && (lane & 15) == 0) { asv[r] = pa; adv[r] = pd; }
    }
}

// ---------------- build adjacency through composed map ----------------
__global__ void build_k(const int* __restrict__ src, const int* __restrict__ dst,
                        int E, const int* __restrict__ map,
                        int* __restrict__ deg, int* __restrict__ adj)
{
    int e = blockIdx.x*blockDim.x + threadIdx.x;
    if (e >= E) return;
    int s = src[e], d = dst[e];
    if (map) {
        s = map[s]; d = map[d];
        if (s < 0 || d < 0) return;
    }
    int pos = atomicAdd(&deg[d], 1);
    if (pos < CAP) adj[(size_t)d*CAP + pos] = s;
}

// ---------------- compose: gmap = map2 ∘ gmap ----------------
__global__ void compose_k(int* __restrict__ gmap, const int* __restrict__ m2, int n)
{
    int i = blockIdx.x*blockDim.x + threadIdx.x;
    if (i >= n) return;
    int g = gmap[i];
    gmap[i] = (g >= 0) ? m2[g] : -1;
}

// ---------------- GAT aggregation + fused pooling score ----------------
__global__ void gat_agg_k(const float* __restrict__ hl, const float* __restrict__ asv,
                          const float* __restrict__ adv, const int* __restrict__ adj,
                          const int* __restrict__ deg, const float* __restrict__ b,
                          float* __restrict__ out, int N,
                          const float* __restrict__ p, const float* __restrict__ nrm,
                          int nidx, float* __restrict__ sc)
{
    int d = (blockIdx.x*blockDim.x + threadIdx.x) >> 5;
    int lane = threadIdx.x & 31;
    if (d >= N) return;
    float add = adv[d];
    // self loop
    float l = asv[d] + add; l = (l > 0.f) ? l : 0.2f*l;
    float w = __expf(l);
    float den0 = w, den1 = 0.f;
    float4 hv = *reinterpret_cast<const float4*>(hl + (size_t)d*128 + lane*4);
    float4 a0 = make_float4(w*hv.x, w*hv.y, w*hv.z, w*hv.w);
    float4 a1 = make_float4(0.f, 0.f, 0.f, 0.f);
    int dg = deg[d]; if (dg > CAP) dg = CAP;
    const int* row = adj + (size_t)d*CAP;
    int j = 0;
    for (; j + 2 <= dg; j += 2) {
        int s0 = row[j], s1 = row[j+1];
        float l0 = asv[s0] + add; l0 = (l0 > 0.f) ? l0 : 0.2f*l0;
        float l1 = asv[s1] + add; l1 = (l1 > 0.f) ? l1 : 0.2f*l1;
        float w0 = __expf(l0), w1 = __expf(l1);
        float4 g0 = *reinterpret_cast<const float4*>(hl + (size_t)s0*128 + lane*4);
        float4 g1 = *reinterpret_cast<const float4*>(hl + (size_t)s1*128 + lane*4);
        den0 += w0; den1 += w1;
        a0.x += w0*g0.x; a0.y += w0*g0.y; a0.z += w0*g0.z; a0.w += w0*g0.w;
        a1.x += w1*g1.x; a1.y += w1*g1.y; a1.z += w1*g1.z; a1.w += w1*g1.w;
    }
    if (j < dg) {
        int s0 = row[j];
        float l0 = asv[s0] + add; l0 = (l0 > 0.f) ? l0 : 0.2f*l0;
        float w0 = __expf(l0);
        float4 g0 = *reinterpret_cast<const float4*>(hl + (size_t)s0*128 + lane*4);
        den0 += w0;
        a0.x += w0*g0.x; a0.y += w0*g0.y; a0.z += w0*g0.z; a0.w += w0*g0.w;
    }
    float inv = 1.f/(den0 + den1);
    float4 bb = *reinterpret_cast<const float4*>(b + lane*4);
    float4 o;
    o.x = fmaxf((a0.x + a1.x)*inv + bb.x, 0.f);
    o.y = fmaxf((a0.y + a1.y)*inv + bb.y, 0.f);
    o.z = fmaxf((a0.z + a1.z)*inv + bb.z, 0.f);
    o.w = fmaxf((a0.w + a1.w)*inv + bb.w, 0.f);
    *reinterpret_cast<float4*>(out + (size_t)d*128 + lane*4) = o;
    // fused pooling score: sc[d] = (out_d . p) / ||p||
    float4 p4 = *reinterpret_cast<const float4*>(p + lane*4);
    float s = o.x*p4.x + o.y*p4.y + o.z*p4.z + o.w*p4.w;
    #pragma unroll
    for (int off = 16; off > 0; off >>= 1) s += __shfl_xor_sync(0xffffffffu, s, off);
    if (lane == 0) sc[d] = s * nrm[nidx];
}

// ---------------- per-graph top-k (bitonic sort; npad = blockDim.x pow2) -------------
__global__ void topk_k(const float* __restrict__ sc, int n, int k,
                       int* __restrict__ perm, int* __restrict__ map)
{
    __shared__ float sval[1024];
    __shared__ int   sidx[1024];
    int g = blockIdx.x, t = threadIdx.x, npad = blockDim.x;
    sval[t] = (t < n) ? sc[g*n + t] : -FINF;
    sidx[t] = t;
    if (t < n) map[g*n + t] = -1;
    __syncthreads();
    for (int kk = 2; kk <= npad; kk <<= 1) {
        for (int j = kk >> 1; j > 0; j >>= 1) {
            int ixj = t ^ j;
            if (ixj > t) {
                bool desc = ((t & kk) == 0);
                float v1 = sval[t], v2 = sval[ixj];
                bool sw = desc ? (v1 < v2) : (v1 > v2);
                if (sw) {
                    sval[t] = v2; sval[ixj] = v1;
                    int tmp = sidx[t]; sidx[t] = sidx[ixj]; sidx[ixj] = tmp;
                }
            }
            __syncthreads();
        }
    }
    if (t < k) {
        int old = g*n + sidx[t];
        perm[g*k + t] = old;
        map[old] = g*k + t;
    }
}

// ---------------- gather pooled features: hp[new] = h[old]*tanh(sc[old]) -------------
__global__ void gather_k(const float* __restrict__ h, const float* __restrict__ sc,
                         const int* __restrict__ perm, float* __restrict__ hp, int Nnew)
{
    int w = (blockIdx.x*blockDim.x + threadIdx.x) >> 5;
    int lane = threadIdx.x & 31;
    if (w >= Nnew) return;
    int old = perm[w];
    float gsc = tanhf(sc[old]);
    float4 v = *reinterpret_cast<const float4*>(h + (size_t)old*128 + lane*4);
    v.x *= gsc; v.y *= gsc; v.z *= gsc; v.w *= gsc;
    *reinterpret_cast<float4*>(hp + (size_t)w*128 + lane*4) = v;
}

// ---------------- readout: z[g] (=|+=) [max | mean] over k rows ----------------
__global__ void readout_k(const float* __restrict__ hp, float* __restrict__ z, int k,
                          int accum)
{
    int g = blockIdx.x, t = threadIdx.x;   // 128 threads
    const float* base = hp + (size_t)g*k*128 + t;
    float m = -FINF, s = 0.f;
    for (int r = 0; r < k; r++) {
        float v = base[(size_t)r*128];
        m = fmaxf(m, v);
        s += v;
    }
    if (accum) {
        z[g*256 + t]       += m;
        z[g*256 + 128 + t] += s / (float)k;
    } else {
        z[g*256 + t]       = m;
        z[g*256 + 128 + t] = s / (float)k;
    }
}

// ---------------- final MLP + log_softmax ----------------
__global__ void mlp_k(const float* __restrict__ z,
                      const float* __restrict__ lw1, const float* __restrict__ lb1,
                      const float* __restrict__ lw2, const float* __restrict__ lb2,
                      const float* __restrict__ lw3, const float* __restrict__ lb3,
                      float* __restrict__ out)
{
    __shared__ float zr[256], t1[128], t2[64], o[10], red[2];
    int g = blockIdx.x, t = threadIdx.x;   // 256 threads
    zr[t] = z[g*256 + t];
    __syncthreads();
    if (t < 128) {
        float a = lb1[t];
        const float* w = lw1 + t*256;
        for (int j = 0; j < 256; j++) a += zr[j]*w[j];
        t1[t] = fmaxf(a, 0.f);
    }
    __syncthreads();
    if (t < 64) {
        float a = lb2[t];
        const float* w = lw2 + t*128;
        for (int j = 0; j < 128; j++) a += t1[j]*w[j];
        t2[t] = fmaxf(a, 0.f);
    }
    __syncthreads();
    if (t < 10) {
        float a = lb3[t];
        const float* w = lw3 + t*64;
        for (int j = 0; j < 64; j++) a += t2[j]*w[j];
        o[t] = a;
    }
    __syncthreads();
    if (t == 0) {
        float m = -FINF;
        for (int i = 0; i < 10; i++) m = fmaxf(m, o[i]);
        float s = 0.f;
        for (int i = 0; i < 10; i++) s += expf(o[i] - m);
        red[0] = m; red[1] = logf(s);
    }
    __syncthreads();
    if (t < 10) out[g*10 + t] = o[t] - red[0] - red[1];
}

// ---------------- host driver ----------------
static inline int cdiv(int a, int b) { return (a + b - 1) / b; }

extern "C" void kernel_launch(void* const* d_in, const int* in_sizes, int n_in,
                              void* d_out, int out_size)
{
    const float* x   = (const float*)d_in[0];
    const int*   ei  = (const int*)  d_in[1];
    const float* W1  = (const float*)d_in[2];
    const float* aS1 = (const float*)d_in[3];
    const float* aD1 = (const float*)d_in[4];
    const float* b1  = (const float*)d_in[5];
    const float* W2  = (const float*)d_in[6];
    const float* aS2 = (const float*)d_in[7];
    const float* aD2 = (const float*)d_in[8];
    const float* b2  = (const float*)d_in[9];
    const float* W3  = (const float*)d_in[10];
    const float* aS3 = (const float*)d_in[11];
    const float* aD3 = (const float*)d_in[12];
    const float* b3  = (const float*)d_in[13];
    const float* p1  = (const float*)d_in[14];
    const float* p2  = (const float*)d_in[15];
    const float* lw1 = (const float*)d_in[16];
    const float* lb1 = (const float*)d_in[17];
    const float* lw2 = (const float*)d_in[18];
    const float* lb2 = (const float*)d_in[19];
    const float* lw3 = (const float*)d_in[20];
    const float* lb3 = (const float*)d_in[21];
    float* out = (float*)d_out;

    const int E = in_sizes[1] / 2;

    void *p_hl, *p_h, *p_hp, *p_as, *p_ad, *p_sc, *p_deg, *p_adj, *p_perm;
    void *p_gmap, *p_map2, *p_z, *p_nrm;
    cudaGetSymbolAddress(&p_hl, g_hl);   cudaGetSymbolAddress(&p_h, g_h);
    cudaGetSymbolAddress(&p_hp, g_hp);   cudaGetSymbolAddress(&p_as, g_as);
    cudaGetSymbolAddress(&p_ad, g_ad);   cudaGetSymbolAddress(&p_sc, g_sc);
    cudaGetSymbolAddress(&p_deg, g_deg); cudaGetSymbolAddress(&p_adj, g_adj);
    cudaGetSymbolAddress(&p_perm, g_perm);
    cudaGetSymbolAddress(&p_gmap, g_gmap); cudaGetSymbolAddress(&p_map2, g_map2);
    cudaGetSymbolAddress(&p_z, g_z);       cudaGetSymbolAddress(&p_nrm, g_norms);

    float* hl  = (float*)p_hl;  float* h   = (float*)p_h;   float* hp = (float*)p_hp;
    float* asv = (float*)p_as;  float* adv = (float*)p_ad;  float* sc = (float*)p_sc;
    int* deg = (int*)p_deg;     int* adj = (int*)p_adj;
    int* perm = (int*)p_perm;
    int* gmap = (int*)p_gmap;   int* m2 = (int*)p_map2;
    float* z = (float*)p_z;     float* nrm = (float*)p_nrm;

    cudaFuncSetAttribute(gemm128_k, cudaFuncAttributeMaxDynamicSharedMemorySize, GEMM_SMEM);

    norms_k<<<1, 128>>>(p1, p2, nrm);

    // ---------- stage 1 ----------
    gemm128_k<<<cdiv(N1, 128), 256, GEMM_SMEM>>>(x, W1, hl, N1, aS1, aD1, asv, adv);
    zeroI_k<<<cdiv(N1, 256), 256>>>(deg, N1);
    build_k<<<cdiv(E, 256), 256>>>(ei, ei + E, E, nullptr, deg, adj);
    gat_agg_k<<<cdiv(N1, 8), 256>>>(hl, asv, adv, adj, deg, b1, h, N1, p1, nrm, 0, sc);
    topk_k<<<G_NUM, 1024>>>(sc, NPER, K1, perm, gmap);
    gather_k<<<cdiv(N2, 8), 256>>>(h, sc, perm, hp, N2);
    readout_k<<<G_NUM, 128>>>(hp, z, K1, 0);
    zeroI_k<<<cdiv(N2, 256), 256>>>(deg, N2);
    build_k<<<cdiv(E, 256), 256>>>(ei, ei + E, E, gmap, deg, adj);

    // ---------- stage 2 ----------
    gemm128_k<<<cdiv(N2, 128), 256, GEMM_SMEM>>>(hp, W2, hl, N2, aS2, aD2, asv, adv);
    gat_agg_k<<<cdiv(N2, 8), 256>>>(hl, asv, adv, adj, deg, b2, h, N2, p2, nrm, 1, sc);
    topk_k<<<G_NUM, 1024>>>(sc, K1, K2, perm, m2);
    compose_k<<<cdiv(N1, 256), 256>>>(gmap, m2, N1);
    gather_k<<<cdiv(N3, 8), 256>>>(h, sc, perm, hp, N3);
    readout_k<<<G_NUM, 128>>>(hp, z, K2, 1);
    zeroI_k<<<cdiv(N3, 256), 256>>>(deg, N3);
    build_k<<<cdiv(E, 256), 256>>>(ei, ei + E, E, gmap, deg, adj);

    // ---------- stage 3 ----------
    gemm128_k<<<cdiv(N3, 128), 256, GEMM_SMEM>>>(hp, W3, hl, N3, aS3, aD3, asv, adv);
    gat_agg_k<<<cdiv(N3, 8), 256>>>(hl, asv, adv, adj, deg, b3, h, N3, p2, nrm, 1, sc);
    topk_k<<<G_NUM, 512>>>(sc, K2, K3, perm, m2);
    gather_k<<<cdiv(N4, 8), 256>>>(h, sc, perm, hp, N4);
    readout_k<<<G_NUM, 128>>>(hp, z, K3, 1);

    // ---------- head ----------
    mlp_k<<<G_NUM, 256>>>(z, lw1, lb1, lw2, lb2, lw3, lb3, out);
}